// round 7
// baseline (speedup 1.0000x reference)
#include <cuda_runtime.h>
#include <math.h>

#define NN 16384
#define DD 64
#define KK 8
#define EE (NN*KK)
#define TS 64          // src rows per block (2 per thread)
#define NT 128         // threads per knn block
#define NG 4           // dst-split groups (1 warp each)
#define TD 16          // dst rows per tile per group
#define MM 10          // top candidates kept per (thread,row)
#define NC 10          // merged candidates per row for refine
#define CAP 5          // per-(thread,row) append buffer capacity
#define RR 32          // rows per refine block

#define F_INF __int_as_float(0x7f800000)
typedef unsigned long long ull;

// ---------------- device scratch (static, no allocation) ----------------
__device__ double g_sqs64[NN];
__device__ double g_sqd64[NN];
__device__ float  g_sqdF[NN];
__device__ int    g_dstStart[8];
__device__ int    g_dstEnd[8];
__device__ int    g_cand[NN * NC];
__device__ float  g_lik[EE];
__device__ float  g_wtmp[EE];
__device__ float  g_psum[128];
__device__ float  g_psq[128];
__device__ float  g_pw[128];

// ---------------- packed f32x2 helpers (sm_103a) ----------------
__device__ __forceinline__ void upk2(ull v, float& a, float& b) {
    asm("mov.b64 {%0, %1}, %2;" : "=f"(a), "=f"(b) : "l"(v));
}
__device__ __forceinline__ ull fma2(ull a, ull b, ull c) {
    ull r;
    asm("fma.rn.f32x2 %0, %1, %2, %3;" : "=l"(r) : "l"(a), "l"(b), "l"(c));
    return r;
}
__device__ __forceinline__ ull add2(ull a, ull b) {
    ull r;
    asm("add.rn.f32x2 %0, %1, %2;" : "=l"(r) : "l"(a), "l"(b));
    return r;
}
__device__ __forceinline__ float red2(ull a, ull b) {
    float x, y;
    upk2(add2(a, b), x, y);
    return x + y;
}

// Replace current worst slot with (SC,IX); recompute worst.
#define TOPK_INSERT(SC, IX) do {                                              \
    _Pragma("unroll")                                                         \
    for (int _s = 0; _s < MM; _s++)                                           \
        if (_s == worstSlot) { tsc[_s] = (SC); tidx[_s] = (IX); }             \
    worst = tsc[0]; worstSlot = 0;                                            \
    _Pragma("unroll")                                                         \
    for (int _s = 1; _s < MM; _s++)                                           \
        if (tsc[_s] > worst) { worst = tsc[_s]; worstSlot = _s; }             \
} while (0)

// Flush a per-thread append buffer into its smem top-MM list.
#define FLUSH(BUF, LSC, LIX, WORST, CNT) do {                                 \
    float tsc[MM]; int tidx[MM];                                              \
    _Pragma("unroll")                                                         \
    for (int _s = 0; _s < MM; _s++) { tsc[_s] = LSC[_s][tid]; tidx[_s] = LIX[_s][tid]; } \
    float worst = tsc[0]; int worstSlot = 0;                                  \
    _Pragma("unroll")                                                         \
    for (int _s = 1; _s < MM; _s++)                                           \
        if (tsc[_s] > worst) { worst = tsc[_s]; worstSlot = _s; }             \
    _Pragma("unroll 1")                                                       \
    for (int _k = 0; _k < (CNT); _k++) {                                      \
        ull _v = BUF[_k][tid];                                                \
        float _sc = __uint_as_float((unsigned)(_v >> 32));                    \
        int _ix = (int)(_v & 0xffffffffu);                                    \
        if (_sc < worst) { TOPK_INSERT(_sc, _ix); }                           \
    }                                                                         \
    _Pragma("unroll")                                                         \
    for (int _s = 0; _s < MM; _s++) { LSC[_s][tid] = tsc[_s]; LIX[_s][tid] = tidx[_s]; } \
    WORST = worst; CNT = 0;                                                   \
} while (0)

// ---------------- K0a: dst fp64 norms ----------------
__global__ void prep_dst_kernel(const float* __restrict__ dst) {
    int j = blockIdx.x * blockDim.x + threadIdx.x;
    const float4* pd = (const float4*)(dst + (size_t)j * DD);
    double sd = 0.0;
#pragma unroll
    for (int q = 0; q < 16; q++) {
        float4 b = pd[q];
        sd = fma((double)b.x, (double)b.x, sd);
        sd = fma((double)b.y, (double)b.y, sd);
        sd = fma((double)b.z, (double)b.z, sd);
        sd = fma((double)b.w, (double)b.w, sd);
    }
    g_sqd64[j] = sd;
    g_sqdF[j] = (float)sd;
}

// ---------------- K0b: src fp64 norms ----------------
__global__ void prep_src_kernel(const float* __restrict__ src) {
    int j = blockIdx.x * blockDim.x + threadIdx.x;
    const float4* ps = (const float4*)(src + (size_t)j * DD);
    double ss = 0.0;
#pragma unroll
    for (int q = 0; q < 16; q++) {
        float4 a = ps[q];
        ss = fma((double)a.x, (double)a.x, ss);
        ss = fma((double)a.y, (double)a.y, ss);
        ss = fma((double)a.z, (double)a.z, ss);
        ss = fma((double)a.w, (double)a.w, ss);
    }
    g_sqs64[j] = ss;
}

// ---------------- K0c: batch boundaries ----------------
__global__ void bounds_kernel(const int* __restrict__ db) {
    int j = blockIdx.x * blockDim.x + threadIdx.x;
    if (j >= NN) return;
    int b = db[j];
    if (j == 0 || db[j - 1] != b) g_dstStart[b] = j;
    if (j == NN - 1 || db[j + 1] != b) g_dstEnd[b] = j + 1;
}

// ---------------- K1: phase A — 2 src rows/thread, buffered select ----------------
__global__ __launch_bounds__(NT, 2)
void knn_kernel(const float* __restrict__ src, const float* __restrict__ dst,
                const int* __restrict__ sb) {
    __shared__ float s_tile[NG][TD * DD];        // 16 KB
    __shared__ float s_sqd[NG][TD];              // 256 B
    __shared__ ull   s_bufA[CAP][NT];            // 5 KB
    __shared__ ull   s_bufB[CAP][NT];            // 5 KB
    __shared__ float s_lscA[MM][NT];             // 5 KB
    __shared__ int   s_lixA[MM][NT];             // 5 KB
    __shared__ float s_lscB[MM][NT];             // 5 KB
    __shared__ int   s_lixB[MM][NT];             // 5 KB  => 46.3 KB total

    const int tid = threadIdx.x;
    const int lane = tid & 31;
    const int grp = tid >> 5;                    // warp id == dst-split group
    const int iA = blockIdx.x * TS + lane;       // src row A
    const int iB = iA + 32;                      // src row B

    // two src rows as 64-bit packed fp32 pairs (128 regs)
    ull s2a[DD / 2], s2b[DD / 2];
    {
        const ulonglong2* spA = (const ulonglong2*)(src + (size_t)iA * DD);
        const ulonglong2* spB = (const ulonglong2*)(src + (size_t)iB * DD);
#pragma unroll
        for (int q = 0; q < 16; q++) {
            ulonglong2 vA = spA[q], vB = spB[q];
            s2a[2 * q] = vA.x; s2a[2 * q + 1] = vA.y;
            s2b[2 * q] = vB.x; s2b[2 * q + 1] = vB.y;
        }
    }

    const int loA = g_dstStart[sb[iA]], hiA = g_dstEnd[sb[iA]];
    const int loB = g_dstStart[sb[iB]], hiB = g_dstEnd[sb[iB]];
    const int lo_u = g_dstStart[sb[blockIdx.x * TS]];
    const int hi_u = g_dstEnd[sb[blockIdx.x * TS + TS - 1]];

#pragma unroll
    for (int s = 0; s < MM; s++) {
        s_lscA[s][tid] = F_INF; s_lixA[s][tid] = 0;
        s_lscB[s][tid] = F_INF; s_lixB[s][tid] = 0;
    }
    float worstA = F_INF, worstB = F_INF;
    int cntA = 0, cntB = 0;

    const int nIter = (hi_u - lo_u + NG * TD - 1) / (NG * TD);
#pragma unroll 1
    for (int it = 0; it < nIter; ++it) {
        const int tbase = lo_u + (it * NG + grp) * TD;
        if (tbase >= hi_u) continue;             // warp-uniform
        // skip tiles fully outside BOTH rows' ranges for the whole warp
        bool outA = (tbase >= hiA) || (tbase + TD <= loA);
        bool outB = (tbase >= hiB) || (tbase + TD <= loB);
        if (__all_sync(0xffffffffu, outA && outB)) continue;

        __syncwarp();
        {
            const float4* gp = (const float4*)(dst + (size_t)tbase * DD);
            float4* tp = (float4*)s_tile[grp];
#pragma unroll
            for (int q = 0; q < 8; q++) {
                int f = q * 32 + lane;
                int jj = f >> 4;
                float4 v = make_float4(0.f, 0.f, 0.f, 0.f);
                if (tbase + jj < hi_u) v = gp[f];
                tp[f] = v;
            }
            if (lane < TD) {
                float sq = 0.f;
                if (tbase + lane < hi_u) sq = g_sqdF[tbase + lane];
                s_sqd[grp][lane] = sq;
            }
        }
        __syncwarp();

        const ulonglong2* tb2 = (const ulonglong2*)s_tile[grp];
        bool inA = (tbase >= loA) && (tbase + TD <= hiA);
        bool inB = (tbase >= loB) && (tbase + TD <= hiB);
        const bool fastAll = __all_sync(0xffffffffu, inA && inB);

#pragma unroll 1
        for (int jj = 0; jj < TD; jj += 2) {
            ull a0 = 0, a1 = 0, a2 = 0, a3 = 0;
            ull b0 = 0, b1 = 0, b2 = 0, b3 = 0;
            const ulonglong2* r0 = tb2 + jj * 16;
            const ulonglong2* r1 = r0 + 16;
#pragma unroll
            for (int q = 0; q < 16; q++) {
                ulonglong2 v0 = r0[q], v1 = r1[q];
                a0 = fma2(s2a[2 * q],     v0.x, a0);
                a1 = fma2(s2a[2 * q + 1], v0.y, a1);
                a2 = fma2(s2a[2 * q],     v1.x, a2);
                a3 = fma2(s2a[2 * q + 1], v1.y, a3);
                b0 = fma2(s2b[2 * q],     v0.x, b0);
                b1 = fma2(s2b[2 * q + 1], v0.y, b1);
                b2 = fma2(s2b[2 * q],     v1.x, b2);
                b3 = fma2(s2b[2 * q + 1], v1.y, b3);
            }
            float sq0 = s_sqd[grp][jj], sq1 = s_sqd[grp][jj + 1];
            float sa0 = fmaf(-2.f, red2(a0, a1), sq0);
            float sa1 = fmaf(-2.f, red2(a2, a3), sq1);
            float sb0 = fmaf(-2.f, red2(b0, b1), sq0);
            float sb1 = fmaf(-2.f, red2(b2, b3), sq1);
            int j0 = tbase + jj, j1 = j0 + 1;

            bool okA0 = sa0 < worstA, okA1 = sa1 < worstA;
            bool okB0 = sb0 < worstB, okB1 = sb1 < worstB;
            if (!fastAll) {
                okA0 = okA0 && (j0 >= loA) && (j0 < hiA);
                okA1 = okA1 && (j1 >= loA) && (j1 < hiA);
                okB0 = okB0 && (j0 >= loB) && (j0 < hiB);
                okB1 = okB1 && (j1 >= loB) && (j1 < hiB);
            }
            if (okA0) { s_bufA[cntA][tid] = ((ull)__float_as_uint(sa0) << 32) | (unsigned)j0; cntA++; }
            if (okA1) { s_bufA[cntA][tid] = ((ull)__float_as_uint(sa1) << 32) | (unsigned)j1; cntA++; }
            if (okB0) { s_bufB[cntB][tid] = ((ull)__float_as_uint(sb0) << 32) | (unsigned)j0; cntB++; }
            if (okB1) { s_bufB[cntB][tid] = ((ull)__float_as_uint(sb1) << 32) | (unsigned)j1; cntB++; }

            if (__any_sync(0xffffffffu, (cntA >= CAP - 2) || (cntB >= CAP - 2))) {
                FLUSH(s_bufA, s_lscA, s_lixA, worstA, cntA);
                FLUSH(s_bufB, s_lscB, s_lixB, worstB, cntB);
            }
        }
    }

    // final flush of leftovers
    FLUSH(s_bufA, s_lscA, s_lixA, worstA, cntA);
    FLUSH(s_bufB, s_lscB, s_lixB, worstB, cntB);

    // cross-warp merge: warp 0 -> rows A (lane), warp 1 -> rows B (lane+32)
    __syncthreads();
    if (grp < 2) {
        float (*lsc)[NT] = (grp == 0) ? s_lscA : s_lscB;
        int (*lix)[NT] = (grp == 0) ? s_lixA : s_lixB;
        float tsc[MM]; int tidx[MM];
#pragma unroll
        for (int s = 0; s < MM; s++) { tsc[s] = lsc[s][lane]; tidx[s] = lix[s][lane]; }
        float worst = tsc[0]; int worstSlot = 0;
#pragma unroll
        for (int s = 1; s < MM; s++)
            if (tsc[s] > worst) { worst = tsc[s]; worstSlot = s; }
#pragma unroll 1
        for (int g = 1; g < NG; g++) {
#pragma unroll
            for (int s = 0; s < MM; s++) {
                float sc = lsc[s][g * 32 + lane];
                int ix = lix[s][g * 32 + lane];
                if (sc < worst) { TOPK_INSERT(sc, ix); }
            }
        }
        const int row = blockIdx.x * TS + lane + (grp == 1 ? 32 : 0);
#pragma unroll
        for (int s = 0; s < NC; s++) {
            int v = (tsc[s] == F_INF) ? (-1 - s) : tidx[s];
            g_cand[row * NC + s] = v;
        }
    }
}

// ---------------- K2: phase B — fp64 refine + reference-grid ranking ----------------
__global__ __launch_bounds__(RR * NC)
void refine_kernel(const float* __restrict__ src, const float* __restrict__ dst,
                   float* g0, float* g1) {
    __shared__ double sD[RR][DD];
    __shared__ float s_sc[RR][NC];
    __shared__ int s_ix[RR][NC];

    const int t = threadIdx.x;
    const int r = t / NC;
    const int c = t % NC;
    const int i0 = blockIdx.x * RR;
    const int i = i0 + r;

    for (int e = t; e < RR * DD; e += RR * NC)
        sD[e >> 6][e & 63] = (double)src[(size_t)i0 * DD + e];
    __syncthreads();

    const int idx = g_cand[i * NC + c];
    float sc;
    double dot = 0.0;
    if (idx >= 0) {
        const float4* dp = (const float4*)(dst + (size_t)idx * DD);
        double d0 = 0.0, d1 = 0.0;
#pragma unroll
        for (int q = 0; q < 16; q++) {
            float4 v = __ldg(dp + q);
            d0 = fma(sD[r][4 * q + 0], (double)v.x, d0);
            d1 = fma(sD[r][4 * q + 1], (double)v.y, d1);
            d0 = fma(sD[r][4 * q + 2], (double)v.z, d0);
            d1 = fma(sD[r][4 * q + 3], (double)v.w, d1);
        }
        dot = d0 + d1;
        float sqs32 = (float)g_sqs64[i];
        float sqd32 = (float)g_sqd64[idx];
        float dot32 = (float)dot;
        sc = __fadd_rn(__fadd_rn(sqs32, __fmul_rn(-2.f, dot32)), sqd32);
    } else {
        sc = F_INF;
    }
    s_sc[r][c] = sc;
    s_ix[r][c] = idx;
    __syncthreads();

    int rank = 0;
#pragma unroll
    for (int m = 0; m < NC; m++) {
        float o = s_sc[r][m];
        int oi = s_ix[r][m];
        rank += (o < sc) || (o == sc && oi < idx);
    }
    if (rank < KK) {
        int e = i * KK + rank;
        if (g0) g0[e] = (float)i;
        if (g1) g1[e] = (float)idx;
        g_lik[e] = (float)dot;
    }
}

// ---------------- K3: deterministic partial sums of likelihood ----------------
__global__ void red1_kernel() {
    __shared__ float ss[256], sq[256];
    int t = threadIdx.x, b = blockIdx.x;
    float s = 0.f, q = 0.f;
#pragma unroll
    for (int k = 0; k < 4; k++) {
        float x = g_lik[b * 1024 + k * 256 + t];
        s += x; q += x * x;
    }
    ss[t] = s; sq[t] = q;
    __syncthreads();
    for (int off = 128; off > 0; off >>= 1) {
        if (t < off) { ss[t] += ss[t + off]; sq[t] += sq[t + off]; }
        __syncthreads();
    }
    if (t == 0) { g_psum[b] = ss[0]; g_psq[b] = sq[0]; }
}

// ---------------- K4: finalize stats + sigmoid + partial w-sums ----------------
__global__ void bn_kernel(const float* __restrict__ gamma,
                          const float* __restrict__ beta) {
    __shared__ float ss[256], sq[256];
    int t = threadIdx.x, b = blockIdx.x;
    ss[t] = (t < 128) ? g_psum[t] : 0.f;
    sq[t] = (t < 128) ? g_psq[t] : 0.f;
    __syncthreads();
    for (int off = 128; off > 0; off >>= 1) {
        if (t < off) { ss[t] += ss[t + off]; sq[t] += sq[t + off]; }
        __syncthreads();
    }
    float mean = ss[0] / (float)EE;
    float var = sq[0] / (float)EE - mean * mean;
    float rstd = rsqrtf(var + 1e-5f);
    float a = rstd * gamma[0];
    float c = beta[0] - mean * a;
    __syncthreads();
    float s = 0.f;
#pragma unroll
    for (int k = 0; k < 4; k++) {
        int e = b * 1024 + k * 256 + t;
        float x = g_lik[e];
        float w = 1.f / (1.f + expf(-(x * a + c)));
        g_wtmp[e] = w;
        s += w;
    }
    ss[t] = s;
    __syncthreads();
    for (int off = 128; off > 0; off >>= 1) {
        if (t < off) ss[t] += ss[t + off];
        __syncthreads();
    }
    if (t == 0) g_pw[b] = ss[0];
}

// ---------------- K5: finalize w-mean + scale ----------------
__global__ void scale_kernel(float* wout) {
    __shared__ float ss[256];
    int t = threadIdx.x, b = blockIdx.x;
    ss[t] = (t < 128) ? g_pw[t] : 0.f;
    __syncthreads();
    for (int off = 128; off > 0; off >>= 1) {
        if (t < off) ss[t] += ss[t + off];
        __syncthreads();
    }
    float inv = (float)EE / ss[0];
    if (!wout) return;
#pragma unroll
    for (int k = 0; k < 4; k++) {
        int e = b * 1024 + k * 256 + t;
        wout[e] = g_wtmp[e] * inv;
    }
}

// ---------------- launch ----------------
extern "C" void kernel_launch(void* const* d_in, const int* in_sizes, int n_in,
                              void* d_out, int out_size) {
    const float* src = (const float*)d_in[0];
    const float* dst = (const float*)d_in[1];
    const int* sb = (const int*)d_in[2];
    const int* db = (const int*)d_in[3];
    const float* gamma = (const float*)d_in[4];
    const float* beta = (const float*)d_in[5];

    float* out = (float*)d_out;
    float* g0 = nullptr;
    float* g1 = nullptr;
    float* wout = nullptr;
    if (out_size >= 3 * EE) {
        g0 = out; g1 = out + EE; wout = out + 2 * EE;
    } else if (out_size >= 2 * EE) {
        g0 = out; g1 = out + EE;
    } else {
        wout = out;
    }

    prep_dst_kernel<<<NN / 128, 128>>>(dst);        // launch 1
    prep_src_kernel<<<NN / 128, 128>>>(src);        // launch 2
    bounds_kernel<<<NN / 128, 128>>>(db);           // launch 3
    knn_kernel<<<NN / TS, NT>>>(src, dst, sb);      // launch 4 (ncu capture slot)
    refine_kernel<<<NN / RR, RR * NC>>>(src, dst, g0, g1);
    red1_kernel<<<128, 256>>>();
    bn_kernel<<<128, 256>>>(gamma, beta);
    scale_kernel<<<128, 256>>>(wout);
}

// round 9
// speedup vs baseline: 1.1845x; 1.1845x over previous
#include <cuda_runtime.h>
#include <cuda_bf16.h>
#include <math.h>
#include <stdint.h>

#define NN 16384
#define DD 64
#define KK 8
#define EE (NN*KK)
#define NT 64          // threads per knn block (2 warps)
#define RPB 64         // src rows per block
#define TDT 64         // dst rows per smem tile
#define MM 10          // candidates kept per src row
#define NC 10          // candidates consumed by refine
#define CAP 8          // per-thread append buffer capacity
#define RR 32          // rows per refine block

#define F_INF __int_as_float(0x7f800000)
typedef unsigned long long ull;

// ---------------- device scratch (static, no allocation) ----------------
__device__ double g_sqs64[NN];
__device__ double g_sqd64[NN];
__device__ float  g_sqdF[NN];
__device__ __nv_bfloat16 g_srcb[NN * DD];
__device__ __nv_bfloat16 g_dstb[NN * DD];
__device__ int    g_dstStart[8];
__device__ int    g_dstEnd[8];
__device__ int    g_cand[NN * NC];
__device__ float  g_lik[EE];
__device__ float  g_wtmp[EE];
__device__ float  g_psum[128];
__device__ float  g_psq[128];
__device__ float  g_pw[128];

// ---------------- warp MMA (sm_80-era PTX; maps to HMMA on sm_103) -------
#define MMA_BF16(D0, D1, D2, D3, A, B0, B1)                                   \
    asm volatile(                                                             \
        "mma.sync.aligned.m16n8k16.row.col.f32.bf16.bf16.f32 "                \
        "{%0,%1,%2,%3}, {%4,%5,%6,%7}, {%8,%9}, {%0,%1,%2,%3};"               \
        : "+f"(D0), "+f"(D1), "+f"(D2), "+f"(D3)                              \
        : "r"((A)[0]), "r"((A)[1]), "r"((A)[2]), "r"((A)[3]),                 \
          "r"(B0), "r"(B1))

// Replace current worst slot; recompute worst. (names: tsc/tidx/fw/fws)
#define LIST_INSERT(SC, IX) do {                                              \
    _Pragma("unroll")                                                         \
    for (int _s = 0; _s < MM; _s++)                                           \
        if (_s == fws) { tsc[_s] = (SC); tidx[_s] = (IX); }                   \
    fw = tsc[0]; fws = 0;                                                     \
    _Pragma("unroll")                                                         \
    for (int _s = 1; _s < MM; _s++)                                           \
        if (tsc[_s] > fw) { fw = tsc[_s]; fws = _s; }                         \
} while (0)

// Flush append buffer into this thread's smem top-MM list; UPDATE thresh.
#define FLUSHX() do {                                                         \
    float tsc[MM]; int tidx[MM];                                              \
    _Pragma("unroll")                                                         \
    for (int _s = 0; _s < MM; _s++) { tsc[_s] = s_lsc[_s][tid]; tidx[_s] = s_lix[_s][tid]; } \
    float fw = tsc[0]; int fws = 0;                                           \
    _Pragma("unroll")                                                         \
    for (int _s = 1; _s < MM; _s++)                                           \
        if (tsc[_s] > fw) { fw = tsc[_s]; fws = _s; }                         \
    _Pragma("unroll 1")                                                       \
    for (int _k = 0; _k < cnt; _k++) {                                        \
        ull _v = s_buf[_k][tid];                                              \
        float _sc = __uint_as_float((unsigned)(_v >> 32));                    \
        int _ix = (int)(_v & 0xffffffffu);                                    \
        if (_sc < fw) { LIST_INSERT(_sc, _ix); }                              \
    }                                                                         \
    _Pragma("unroll")                                                         \
    for (int _s = 0; _s < MM; _s++) { s_lsc[_s][tid] = tsc[_s]; s_lix[_s][tid] = tidx[_s]; } \
    thresh = fw; cnt = 0;                                                     \
} while (0)

// ---------------- K0a: dst norms + bf16 convert ----------------
__global__ void prep_dst_kernel(const float* __restrict__ dst) {
    int j = blockIdx.x * blockDim.x + threadIdx.x;
    const float4* pd = (const float4*)(dst + (size_t)j * DD);
    __nv_bfloat162* ob = (__nv_bfloat162*)(g_dstb + (size_t)j * DD);
    double sd = 0.0;
#pragma unroll
    for (int q = 0; q < 16; q++) {
        float4 b = pd[q];
        sd = fma((double)b.x, (double)b.x, sd);
        sd = fma((double)b.y, (double)b.y, sd);
        sd = fma((double)b.z, (double)b.z, sd);
        sd = fma((double)b.w, (double)b.w, sd);
        ob[2 * q]     = __float22bfloat162_rn(make_float2(b.x, b.y));
        ob[2 * q + 1] = __float22bfloat162_rn(make_float2(b.z, b.w));
    }
    g_sqd64[j] = sd;
    g_sqdF[j] = (float)sd;
}

// ---------------- K0b: src norms + bf16 convert ----------------
__global__ void prep_src_kernel(const float* __restrict__ src) {
    int j = blockIdx.x * blockDim.x + threadIdx.x;
    const float4* ps = (const float4*)(src + (size_t)j * DD);
    __nv_bfloat162* ob = (__nv_bfloat162*)(g_srcb + (size_t)j * DD);
    double ss = 0.0;
#pragma unroll
    for (int q = 0; q < 16; q++) {
        float4 a = ps[q];
        ss = fma((double)a.x, (double)a.x, ss);
        ss = fma((double)a.y, (double)a.y, ss);
        ss = fma((double)a.z, (double)a.z, ss);
        ss = fma((double)a.w, (double)a.w, ss);
        ob[2 * q]     = __float22bfloat162_rn(make_float2(a.x, a.y));
        ob[2 * q + 1] = __float22bfloat162_rn(make_float2(a.z, a.w));
    }
    g_sqs64[j] = ss;
}

// ---------------- K0c: batch boundaries ----------------
__global__ void bounds_kernel(const int* __restrict__ db) {
    int j = blockIdx.x * blockDim.x + threadIdx.x;
    if (j >= NN) return;
    int b = db[j];
    if (j == 0 || db[j - 1] != b) g_dstStart[b] = j;
    if (j == NN - 1 || db[j + 1] != b) g_dstEnd[b] = j + 1;
}

// ---------------- K1: phase A — warp-MMA bf16 candidate generation ----------
__global__ __launch_bounds__(NT, 8)
void knn_mma_kernel(const int* __restrict__ sb) {
    __shared__ __align__(16) uint8_t s_b[TDT * 128];   // 8 KB swizzled bf16 tile
    __shared__ float s_sqdt[TDT];                       // 256 B
    __shared__ float s_d[2][32][34];                    // 8.7 KB D transpose
    __shared__ float s_lsc[MM][NT];                     // 2.5 KB
    __shared__ int   s_lix[MM][NT];                     // 2.5 KB
    __shared__ ull   s_buf[CAP][NT];                    // 4 KB

    const int tid = threadIdx.x;
    const int lane = tid & 31;
    const int w = tid >> 5;                  // warp id (0,1)
    const int g = lane >> 2, t4 = lane & 3;  // mma group / thread-in-group
    const int rowbase = blockIdx.x * RPB + w * 32;
    const int i = blockIdx.x * RPB + tid;    // this thread's src row

    // ---- A fragments: warp's 32 src rows x K64, canonical m16n8k16 layout
    uint32_t afr[2][4][4];
#pragma unroll
    for (int mt = 0; mt < 2; mt++)
#pragma unroll
        for (int kt = 0; kt < 4; kt++) {
            const __nv_bfloat16* a0 =
                g_srcb + (size_t)(rowbase + mt * 16 + g) * DD + kt * 16 + 2 * t4;
            const __nv_bfloat16* a1 = a0 + 8 * DD;
            afr[mt][kt][0] = *(const uint32_t*)a0;
            afr[mt][kt][1] = *(const uint32_t*)a1;
            afr[mt][kt][2] = *(const uint32_t*)(a0 + 8);
            afr[mt][kt][3] = *(const uint32_t*)(a1 + 8);
        }

    const int lo_i = g_dstStart[sb[i]];
    const int hi_i = g_dstEnd[sb[i]];
    const int lo_u = g_dstStart[sb[blockIdx.x * RPB]];
    const int hi_u = g_dstEnd[sb[blockIdx.x * RPB + RPB - 1]];
    const int lo_w = g_dstStart[sb[rowbase]];
    const int hi_w = g_dstEnd[sb[rowbase + 31]];

#pragma unroll
    for (int s = 0; s < MM; s++) { s_lsc[s][tid] = F_INF; s_lix[s][tid] = 0; }
    float thresh = F_INF;
    int cnt = 0;

    const int nT = (hi_u - lo_u + TDT - 1) / TDT;
#pragma unroll 1
    for (int t = 0; t < nT; t++) {
        const int tb = lo_u + t * TDT;
        __syncthreads();   // previous tile's selection done
        // cooperative swizzled tile load (64 rows x 128B, 8 x uint4/thread)
#pragma unroll
        for (int u = 0; u < 8; u++) {
            int f = u * NT + tid;
            int row = f >> 3, c16 = f & 7;
            uint4 v = make_uint4(0, 0, 0, 0);
            if (tb + row < hi_u)
                v = *((const uint4*)(g_dstb + (size_t)(tb + row) * DD) + c16);
            unsigned off = (unsigned)(row * 128) + ((unsigned)(((c16 + row) & 7) * 16));
            *(uint4*)(s_b + off) = v;
        }
        s_sqdt[tid] = (tb + tid < hi_u) ? g_sqdF[tb + tid] : F_INF;
        {
            int r2 = tid + NT;  // NT=64==TDT so this covers nothing; keep TDT==NT
            (void)r2;
        }
        __syncthreads();

        // warp-level skip if tile fully outside this warp's batch union
        if (tb >= hi_w || tb + TDT <= lo_w) continue;

#pragma unroll 1
        for (int ch = 0; ch < 2; ch++) {
            const int cb = ch * 32;
            float d[2][4][4];
#pragma unroll
            for (int mt = 0; mt < 2; mt++)
#pragma unroll
                for (int n8 = 0; n8 < 4; n8++)
#pragma unroll
                    for (int r = 0; r < 4; r++) d[mt][n8][r] = 0.f;

#pragma unroll
            for (int kt = 0; kt < 4; kt++) {
#pragma unroll
                for (int n8 = 0; n8 < 4; n8++) {
                    const int n = cb + n8 * 8 + g;              // dst row in tile
                    const unsigned base = (unsigned)(n * 128);
                    const unsigned x = (unsigned)(32 * kt + 4 * t4);   // byte 2k
                    const unsigned off0 = (x + 16u * (unsigned)(n & 7)) & 127u;
                    const unsigned off1 = (off0 + 16u) & 127u;
                    uint32_t b0 = *(const uint32_t*)(s_b + base + off0);
                    uint32_t b1 = *(const uint32_t*)(s_b + base + off1);
                    MMA_BF16(d[0][n8][0], d[0][n8][1], d[0][n8][2], d[0][n8][3],
                             afr[0][kt], b0, b1);
                    MMA_BF16(d[1][n8][0], d[1][n8][1], d[1][n8][2], d[1][n8][3],
                             afr[1][kt], b0, b1);
                }
            }

            // transpose D through smem: row = src row (warp-local), col = n
            __syncwarp();
#pragma unroll
            for (int mt = 0; mt < 2; mt++)
#pragma unroll
                for (int n8 = 0; n8 < 4; n8++) {
                    const int c = n8 * 8 + 2 * t4;
                    *(float2*)&s_d[w][mt * 16 + g][c] =
                        make_float2(d[mt][n8][0], d[mt][n8][1]);
                    *(float2*)&s_d[w][mt * 16 + g + 8][c] =
                        make_float2(d[mt][n8][2], d[mt][n8][3]);
                }
            __syncwarp();

            // gated selection: lane owns src row (rowbase+lane)
            const float* drow = &s_d[w][lane][0];
#pragma unroll
            for (int g4 = 0; g4 < 8; g4++) {
#pragma unroll
                for (int c = 0; c < 4; c++) {
                    const int cc = g4 * 4 + c;
                    const int j = tb + cb + cc;
                    float sc = fmaf(-2.f, drow[cc], s_sqdt[cb + cc]);
                    bool ok = (sc < thresh) && (j >= lo_i) && (j < hi_i);
                    if (ok) {
                        s_buf[cnt][tid] =
                            ((ull)__float_as_uint(sc) << 32) | (unsigned)j;
                        cnt++;
                    }
                }
                if (__any_sync(0xffffffffu, cnt >= CAP - 4)) { FLUSHX(); }
            }
        }
    }

    FLUSHX();
#pragma unroll
    for (int s = 0; s < NC; s++) {
        float sc = s_lsc[s][tid];
        int ix = s_lix[s][tid];
        g_cand[i * NC + s] = (sc == F_INF) ? (-1 - s) : ix;
    }
}

// ---------------- K2: phase B — fp64 refine + reference-grid ranking --------
__global__ __launch_bounds__(RR * NC)
void refine_kernel(const float* __restrict__ src, const float* __restrict__ dst,
                   float* g0, float* g1) {
    __shared__ double sD[RR][DD];
    __shared__ float s_sc[RR][NC];
    __shared__ int s_ix[RR][NC];

    const int t = threadIdx.x;
    const int r = t / NC;
    const int c = t % NC;
    const int i0 = blockIdx.x * RR;
    const int i = i0 + r;

    for (int e = t; e < RR * DD; e += RR * NC)
        sD[e >> 6][e & 63] = (double)src[(size_t)i0 * DD + e];
    __syncthreads();

    const int idx = g_cand[i * NC + c];
    float sc;
    double dot = 0.0;
    if (idx >= 0) {
        const float4* dp = (const float4*)(dst + (size_t)idx * DD);
        double d0 = 0.0, d1 = 0.0;
#pragma unroll
        for (int q = 0; q < 16; q++) {
            float4 v = __ldg(dp + q);
            d0 = fma(sD[r][4 * q + 0], (double)v.x, d0);
            d1 = fma(sD[r][4 * q + 1], (double)v.y, d1);
            d0 = fma(sD[r][4 * q + 2], (double)v.z, d0);
            d1 = fma(sD[r][4 * q + 3], (double)v.w, d1);
        }
        dot = d0 + d1;
        float sqs32 = (float)g_sqs64[i];
        float sqd32 = (float)g_sqd64[idx];
        float dot32 = (float)dot;
        sc = __fadd_rn(__fadd_rn(sqs32, __fmul_rn(-2.f, dot32)), sqd32);
    } else {
        sc = F_INF;
    }
    s_sc[r][c] = sc;
    s_ix[r][c] = idx;
    __syncthreads();

    int rank = 0;
#pragma unroll
    for (int m = 0; m < NC; m++) {
        float o = s_sc[r][m];
        int oi = s_ix[r][m];
        rank += (o < sc) || (o == sc && oi < idx);
    }
    if (rank < KK) {
        int e = i * KK + rank;
        if (g0) g0[e] = (float)i;
        if (g1) g1[e] = (float)idx;
        g_lik[e] = (float)dot;
    }
}

// ---------------- K3/K4/K5: epilogue (deterministic) ----------------
__global__ void red1_kernel() {
    __shared__ float ss[256], sq[256];
    int t = threadIdx.x, b = blockIdx.x;
    float s = 0.f, q = 0.f;
#pragma unroll
    for (int k = 0; k < 4; k++) {
        float x = g_lik[b * 1024 + k * 256 + t];
        s += x; q += x * x;
    }
    ss[t] = s; sq[t] = q;
    __syncthreads();
    for (int off = 128; off > 0; off >>= 1) {
        if (t < off) { ss[t] += ss[t + off]; sq[t] += sq[t + off]; }
        __syncthreads();
    }
    if (t == 0) { g_psum[b] = ss[0]; g_psq[b] = sq[0]; }
}

__global__ void bn_kernel(const float* __restrict__ gamma,
                          const float* __restrict__ beta) {
    __shared__ float ss[256], sq[256];
    int t = threadIdx.x, b = blockIdx.x;
    ss[t] = (t < 128) ? g_psum[t] : 0.f;
    sq[t] = (t < 128) ? g_psq[t] : 0.f;
    __syncthreads();
    for (int off = 128; off > 0; off >>= 1) {
        if (t < off) { ss[t] += ss[t + off]; sq[t] += sq[t + off]; }
        __syncthreads();
    }
    float mean = ss[0] / (float)EE;
    float var = sq[0] / (float)EE - mean * mean;
    float a = rsqrtf(var + 1e-5f) * gamma[0];
    float c = beta[0] - mean * a;
    __syncthreads();
    float s = 0.f;
#pragma unroll
    for (int k = 0; k < 4; k++) {
        int e = b * 1024 + k * 256 + t;
        float x = g_lik[e];
        float w = 1.f / (1.f + expf(-(x * a + c)));
        g_wtmp[e] = w;
        s += w;
    }
    ss[t] = s;
    __syncthreads();
    for (int off = 128; off > 0; off >>= 1) {
        if (t < off) ss[t] += ss[t + off];
        __syncthreads();
    }
    if (t == 0) g_pw[b] = ss[0];
}

__global__ void scale_kernel(float* wout) {
    __shared__ float ss[256];
    int t = threadIdx.x, b = blockIdx.x;
    ss[t] = (t < 128) ? g_pw[t] : 0.f;
    __syncthreads();
    for (int off = 128; off > 0; off >>= 1) {
        if (t < off) ss[t] += ss[t + off];
        __syncthreads();
    }
    float inv = (float)EE / ss[0];
    if (!wout) return;
#pragma unroll
    for (int k = 0; k < 4; k++) {
        int e = b * 1024 + k * 256 + t;
        wout[e] = g_wtmp[e] * inv;
    }
}

// ---------------- launch ----------------
extern "C" void kernel_launch(void* const* d_in, const int* in_sizes, int n_in,
                              void* d_out, int out_size) {
    const float* src = (const float*)d_in[0];
    const float* dst = (const float*)d_in[1];
    const int* sb = (const int*)d_in[2];
    const int* db = (const int*)d_in[3];
    const float* gamma = (const float*)d_in[4];
    const float* beta = (const float*)d_in[5];

    float* out = (float*)d_out;
    float* g0 = nullptr;
    float* g1 = nullptr;
    float* wout = nullptr;
    if (out_size >= 3 * EE) {
        g0 = out; g1 = out + EE; wout = out + 2 * EE;
    } else if (out_size >= 2 * EE) {
        g0 = out; g1 = out + EE;
    } else {
        wout = out;
    }

    prep_dst_kernel<<<NN / 128, 128>>>(dst);        // launch 1
    prep_src_kernel<<<NN / 128, 128>>>(src);        // launch 2
    bounds_kernel<<<NN / 128, 128>>>(db);           // launch 3
    knn_mma_kernel<<<NN / RPB, NT>>>(sb);           // launch 4 (ncu capture slot)
    refine_kernel<<<NN / RR, RR * NC>>>(src, dst, g0, g1);
    red1_kernel<<<128, 256>>>();
    bn_kernel<<<128, 256>>>(gamma, beta);
    scale_kernel<<<128, 256>>>(wout);
}